// round 8
// baseline (speedup 1.0000x reference)
#include <cuda_runtime.h>
#include <cuda_bf16.h>
#include <cstdint>

#define NB 8
#define CC 256
#define NN 4096
#define DD 32
#define BQ 64
#define BK 32
#define NT (NN / BK)

// Pre-split bf16 operands (hi + lo ~ fp32-grade with 3-term products)
__device__ __align__(128) __nv_bfloat16 g_qh[(size_t)NB * NN * DD];
__device__ __align__(128) __nv_bfloat16 g_ql[(size_t)NB * NN * DD];
__device__ __align__(128) __nv_bfloat16 g_kh[(size_t)NB * NN * DD];
__device__ __align__(128) __nv_bfloat16 g_kl[(size_t)NB * NN * DD];
__device__ __align__(128) __nv_bfloat16 g_vh[(size_t)NB * CC * NN];  // [b][c][n]
__device__ __align__(128) __nv_bfloat16 g_vl[(size_t)NB * CC * NN];

// ---- smem layout (dynamic). All strides are 16B-multiples, conflict-free. ----
#define QSTR 80                    // 32 bf16 + pad (20 words)
#define KSTR 80
#define VSTR 80                    // 32 bf16 + pad (20 words)
#define OSTR 260                   // stage stride in floats
#define QH_OFF 0
#define QL_OFF 5120
#define K_OFF(buf, mat) (10240 + (buf) * 5120 + (mat) * 2560)
#define V_OFF(buf, mat) (20480 + (buf) * 40960 + (mat) * 20480)
#define STAGE_OFF 20480            // reuses V region at epilogue (66560 B needed)
#define SMEM_BYTES 102400          // 100 KB -> 2 CTAs/SM

// ---- helpers ----
__device__ __forceinline__ uint32_t smem_u32(const void* p) {
    uint32_t a;
    asm("{ .reg .u64 t; cvta.to.shared.u64 t, %1; cvt.u32.u64 %0, t; }" : "=r"(a) : "l"(p));
    return a;
}
__device__ __forceinline__ void cpa16(uint32_t dst, const void* src) {
    asm volatile("cp.async.cg.shared.global [%0], [%1], 16;" :: "r"(dst), "l"(src) : "memory");
}
__device__ __forceinline__ void cp_commit() { asm volatile("cp.async.commit_group;" ::: "memory"); }
template <int N> __device__ __forceinline__ void cp_wait() {
    asm volatile("cp.async.wait_group %0;" :: "n"(N) : "memory");
}
__device__ __forceinline__ void mma_bf16(float* d, const uint32_t* a, const uint32_t* b) {
    asm volatile(
        "mma.sync.aligned.m16n8k16.row.col.f32.bf16.bf16.f32 "
        "{%0,%1,%2,%3}, {%4,%5,%6,%7}, {%8,%9}, {%0,%1,%2,%3};"
        : "+f"(d[0]), "+f"(d[1]), "+f"(d[2]), "+f"(d[3])
        : "r"(a[0]), "r"(a[1]), "r"(a[2]), "r"(a[3]), "r"(b[0]), "r"(b[1]));
}
__device__ __forceinline__ uint32_t packbf(__nv_bfloat16 lo, __nv_bfloat16 hi) {
    __nv_bfloat162 t; t.x = lo; t.y = hi;
    return *(uint32_t*)&t;
}

// per-thread share of one K/V tile load (9 cp.async of 16B)
__device__ __forceinline__ void load_kv(char* smp, int b, int m0, int buf, int tid) {
    {   // K: 32 rows x 4 chunks x 2 mats = 256 chunks
        int mat = tid >> 7, r = (tid >> 2) & 31, j = tid & 3;
        const __nv_bfloat16* src = (mat ? g_kl : g_kh) +
            ((size_t)(b * NN + m0 + r)) * DD + j * 8;
        cpa16(smem_u32(smp + K_OFF(buf, mat) + r * KSTR + j * 16), src);
    }
#pragma unroll
    for (int it = 0; it < 8; it++) {   // V: 256 rows x 4 chunks x 2 mats = 2048
        int idx = tid + it * 256;
        int mat = idx >> 10, r = (idx >> 2) & 255, j = idx & 3;
        const __nv_bfloat16* src = (mat ? g_vl : g_vh) +
            ((size_t)(b * CC + r)) * NN + m0 + j * 8;
        cpa16(smem_u32(smp + V_OFF(buf, mat) + r * VSTR + j * 16), src);
    }
}

// ---------------------------------------------------------------------------
// Projection: q/k -> [b][n][32] bf16 hi/lo
// ---------------------------------------------------------------------------
__global__ void __launch_bounds__(256) proj_qk(
    const float* __restrict__ W, const float* __restrict__ bias,
    const float* __restrict__ x,
    __nv_bfloat16* __restrict__ oh, __nv_bfloat16* __restrict__ ol)
{
    __shared__ float xs[32][128];
    __shared__ float ws[32][33];
    const int tid = threadIdx.x;
    const int b  = blockIdx.y;
    const int n0 = blockIdx.x * 128;
    const int tr = tid & 7, tn = tid >> 3;

    float acc[4][4];
#pragma unroll
    for (int i = 0; i < 4; i++) {
        float bb = bias[tr * 4 + i];
#pragma unroll
        for (int j = 0; j < 4; j++) acc[i][j] = bb;
    }
    for (int c0 = 0; c0 < CC; c0 += 32) {
#pragma unroll
        for (int k = 0; k < 16; k++) {
            int idx = tid + k * 256;
            int row = idx >> 7, col = idx & 127;
            xs[row][col] = x[((size_t)b * CC + (c0 + row)) * NN + n0 + col];
        }
#pragma unroll
        for (int k = 0; k < 4; k++) {
            int idx = tid + k * 256;
            int row = idx >> 5, col = idx & 31;
            ws[row][col] = W[(size_t)row * CC + c0 + col];
        }
        __syncthreads();
#pragma unroll 8
        for (int cc = 0; cc < 32; cc++) {
            float4 xv = *(const float4*)&xs[cc][tn * 4];
            float wr[4];
#pragma unroll
            for (int i = 0; i < 4; i++) wr[i] = ws[tr * 4 + i][cc];
#pragma unroll
            for (int i = 0; i < 4; i++) {
                acc[i][0] += wr[i] * xv.x; acc[i][1] += wr[i] * xv.y;
                acc[i][2] += wr[i] * xv.z; acc[i][3] += wr[i] * xv.w;
            }
        }
        __syncthreads();
    }
#pragma unroll
    for (int j = 0; j < 4; j++) {
        int n = n0 + tn * 4 + j;
#pragma unroll
        for (int i = 0; i < 4; i++) {
            int r = tr * 4 + i;
            float a = acc[i][j];
            __nv_bfloat16 h = __float2bfloat16(a);
            oh[((size_t)(b * NN + n)) * DD + r] = h;
            ol[((size_t)(b * NN + n)) * DD + r] = __float2bfloat16(a - __bfloat162float(h));
        }
    }
}

// ---------------------------------------------------------------------------
// Projection: v -> [b][c][n] bf16 hi/lo
// ---------------------------------------------------------------------------
__global__ void __launch_bounds__(256) proj_v(
    const float* __restrict__ W, const float* __restrict__ bias,
    const float* __restrict__ x,
    __nv_bfloat16* __restrict__ oh, __nv_bfloat16* __restrict__ ol)
{
    __shared__ float xs[32][128];
    __shared__ float ws[32][33];
    const int tid = threadIdx.x;
    const int b  = blockIdx.y;
    const int n0 = blockIdx.x * 128;
    const int r0 = blockIdx.z * 32;
    const int tr = tid & 7, tn = tid >> 3;

    float acc[4][4];
#pragma unroll
    for (int i = 0; i < 4; i++) {
        float bb = bias[r0 + tr * 4 + i];
#pragma unroll
        for (int j = 0; j < 4; j++) acc[i][j] = bb;
    }
    for (int c0 = 0; c0 < CC; c0 += 32) {
#pragma unroll
        for (int k = 0; k < 16; k++) {
            int idx = tid + k * 256;
            int row = idx >> 7, col = idx & 127;
            xs[row][col] = x[((size_t)b * CC + (c0 + row)) * NN + n0 + col];
        }
#pragma unroll
        for (int k = 0; k < 4; k++) {
            int idx = tid + k * 256;
            int row = idx >> 5, col = idx & 31;
            ws[row][col] = W[(size_t)(r0 + row) * CC + c0 + col];
        }
        __syncthreads();
#pragma unroll 8
        for (int cc = 0; cc < 32; cc++) {
            float4 xv = *(const float4*)&xs[cc][tn * 4];
            float wr[4];
#pragma unroll
            for (int i = 0; i < 4; i++) wr[i] = ws[tr * 4 + i][cc];
#pragma unroll
            for (int i = 0; i < 4; i++) {
                acc[i][0] += wr[i] * xv.x; acc[i][1] += wr[i] * xv.y;
                acc[i][2] += wr[i] * xv.z; acc[i][3] += wr[i] * xv.w;
            }
        }
        __syncthreads();
    }
#pragma unroll
    for (int i = 0; i < 4; i++) {
        int r = r0 + tr * 4 + i;
#pragma unroll
        for (int j = 0; j < 4; j++) {
            int n = n0 + tn * 4 + j;
            float a = acc[i][j];
            __nv_bfloat16 h = __float2bfloat16(a);
            oh[((size_t)(b * CC + r)) * NN + n] = h;
            ol[((size_t)(b * CC + r)) * NN + n] = __float2bfloat16(a - __bfloat162float(h));
        }
    }
}

// ---------------------------------------------------------------------------
// Flash attention via mma.sync (R4 structure: register P, duplicated S),
// BK=32 + 100KB smem -> 2 CTAs/SM for latency hiding.
// Grid (NN/BQ, NB) = (64, 8); 256 threads = 8 warps (4 q-rows x 2 c-halves).
// ---------------------------------------------------------------------------
__global__ void __launch_bounds__(256, 2) flash_mma(
    const float* __restrict__ x, const float* __restrict__ gamma,
    float* __restrict__ out)
{
    extern __shared__ char smp[];
    const int tid  = threadIdx.x;
    const int lane = tid & 31;
    const int wid  = tid >> 5;
    const int wr   = wid >> 1;        // 0..3: q-rows  wr*16..+15
    const int wc   = wid & 1;         // 0..1: channels wc*128..+127
    const int g    = lane >> 2;       // groupID
    const int tg   = lane & 3;        // threadID-in-group
    const int b  = blockIdx.y;
    const int q0 = blockIdx.x * BQ;

    // ---- prologue: Q + tile-0 K/V ----
#pragma unroll
    for (int it = 0; it < 2; it++) {       // Q: 64 rows x 4 chunks x 2 mats
        int idx = tid + it * 256;
        int mat = idx >> 8, r = (idx >> 2) & 63, j = idx & 3;
        const __nv_bfloat16* src = (mat ? g_ql : g_qh) +
            ((size_t)(b * NN + q0 + r)) * DD + j * 8;
        cpa16(smem_u32(smp + (mat ? QL_OFF : QH_OFF) + r * QSTR + j * 16), src);
    }
    load_kv(smp, b, 0, 0, tid);
    cp_commit();
    cp_wait<0>();
    __syncthreads();

    // ---- preload Q fragments (constant across tiles) ----
    uint32_t QhA[2][4], QlA[2][4];
    {
        int rowA = wr * 16 + g, rowB = rowA + 8;
#pragma unroll
        for (int kf = 0; kf < 2; kf++) {
            int w0 = (kf * 8 + tg) * 4;
            QhA[kf][0] = *(const uint32_t*)(smp + QH_OFF + rowA * QSTR + w0);
            QhA[kf][1] = *(const uint32_t*)(smp + QH_OFF + rowB * QSTR + w0);
            QhA[kf][2] = *(const uint32_t*)(smp + QH_OFF + rowA * QSTR + w0 + 16);
            QhA[kf][3] = *(const uint32_t*)(smp + QH_OFF + rowB * QSTR + w0 + 16);
            QlA[kf][0] = *(const uint32_t*)(smp + QL_OFF + rowA * QSTR + w0);
            QlA[kf][1] = *(const uint32_t*)(smp + QL_OFF + rowB * QSTR + w0);
            QlA[kf][2] = *(const uint32_t*)(smp + QL_OFF + rowA * QSTR + w0 + 16);
            QlA[kf][3] = *(const uint32_t*)(smp + QL_OFF + rowB * QSTR + w0 + 16);
        }
    }

    float O[16][4];
#pragma unroll
    for (int i = 0; i < 16; i++)
#pragma unroll
        for (int j = 0; j < 4; j++) O[i][j] = 0.f;
    float lsumA = 0.f, lsumB = 0.f;
    uint32_t Ph[4][2], Pl[4][2];

    for (int t = 0; t < NT; t++) {
        const int buf = t & 1;
        if (t) cp_wait<0>();
        __syncthreads();
        if (t + 1 < NT) { load_kv(smp, b, (t + 1) * BK, buf ^ 1, tid); cp_commit(); }

        // ---- S = Q K^T (both wc warps duplicate; cheap) + exp + pack ----
        const char* kh = smp + K_OFF(buf, 0);
        const char* kl = kh + 2560;
#pragma unroll
        for (int nt = 0; nt < 4; nt++) {
            int krow = nt * 8 + g;
            uint32_t KhB[2][2], KlB[2][2];
#pragma unroll
            for (int kf = 0; kf < 2; kf++) {
                int w0 = (kf * 8 + tg) * 4;
                KhB[kf][0] = *(const uint32_t*)(kh + krow * KSTR + w0);
                KhB[kf][1] = *(const uint32_t*)(kh + krow * KSTR + w0 + 16);
                KlB[kf][0] = *(const uint32_t*)(kl + krow * KSTR + w0);
                KlB[kf][1] = *(const uint32_t*)(kl + krow * KSTR + w0 + 16);
            }
            float S[4] = {0.f, 0.f, 0.f, 0.f};
            mma_bf16(S, QhA[0], KhB[0]); mma_bf16(S, QhA[1], KhB[1]);
            mma_bf16(S, QlA[0], KhB[0]); mma_bf16(S, QlA[1], KhB[1]);
            mma_bf16(S, QhA[0], KlB[0]); mma_bf16(S, QhA[1], KlB[1]);

            float p0 = __expf(S[0]), p1 = __expf(S[1]);
            float p2 = __expf(S[2]), p3 = __expf(S[3]);
            lsumA += p0 + p1;
            lsumB += p2 + p3;
            __nv_bfloat16 h0 = __float2bfloat16(p0), h1 = __float2bfloat16(p1);
            __nv_bfloat16 h2 = __float2bfloat16(p2), h3 = __float2bfloat16(p3);
            Ph[nt][0] = packbf(h0, h1);
            Ph[nt][1] = packbf(h2, h3);
            Pl[nt][0] = packbf(__float2bfloat16(p0 - __bfloat162float(h0)),
                               __float2bfloat16(p1 - __bfloat162float(h1)));
            Pl[nt][1] = packbf(__float2bfloat16(p2 - __bfloat162float(h2)),
                               __float2bfloat16(p3 - __bfloat162float(h3)));
        }

        // ---- O += P V^T (P stays in registers) ----
        const char* vh = smp + V_OFF(buf, 0);
        const char* vl = vh + 20480;
#pragma unroll
        for (int nt = 0; nt < 16; nt++) {
            int crow = wc * 128 + nt * 8 + g;
            uint32_t VhB[2][2], VlB[2][2];
#pragma unroll
            for (int kf = 0; kf < 2; kf++) {
                int w0 = (kf * 8 + tg) * 4;
                VhB[kf][0] = *(const uint32_t*)(vh + crow * VSTR + w0);
                VhB[kf][1] = *(const uint32_t*)(vh + crow * VSTR + w0 + 16);
                VlB[kf][0] = *(const uint32_t*)(vl + crow * VSTR + w0);
                VlB[kf][1] = *(const uint32_t*)(vl + crow * VSTR + w0 + 16);
            }
#pragma unroll
            for (int kf = 0; kf < 2; kf++) {
                uint32_t Ah[4] = {Ph[2*kf][0], Ph[2*kf][1], Ph[2*kf+1][0], Ph[2*kf+1][1]};
                uint32_t Al[4] = {Pl[2*kf][0], Pl[2*kf][1], Pl[2*kf+1][0], Pl[2*kf+1][1]};
                mma_bf16(O[nt], Ah, VhB[kf]);
                mma_bf16(O[nt], Al, VhB[kf]);
                mma_bf16(O[nt], Ah, VlB[kf]);
            }
        }
    }

    // ---- normalize + epilogue ----
    lsumA += __shfl_xor_sync(0xffffffffu, lsumA, 1);
    lsumA += __shfl_xor_sync(0xffffffffu, lsumA, 2);
    lsumB += __shfl_xor_sync(0xffffffffu, lsumB, 1);
    lsumB += __shfl_xor_sync(0xffffffffu, lsumB, 2);
    const float gm = gamma[0];
    const float scA = gm / lsumA;
    const float scB = gm / lsumB;

    __syncthreads();                            // V reads done; reuse as stage
    float* stage = (float*)(smp + STAGE_OFF);   // [q=64][c=256], stride OSTR
    {
        int q = wr * 16 + g;
#pragma unroll
        for (int nt = 0; nt < 16; nt++) {
            int c = wc * 128 + nt * 8 + tg * 2;
            stage[q * OSTR + c]           = O[nt][0] * scA;
            stage[q * OSTR + c + 1]       = O[nt][1] * scA;
            stage[(q + 8) * OSTR + c]     = O[nt][2] * scB;
            stage[(q + 8) * OSTR + c + 1] = O[nt][3] * scB;
        }
    }
    __syncthreads();

    {
        int c = tid;   // one channel row per thread
        const float* xr  = x   + ((size_t)(b * CC + c)) * NN + q0;
        float*       orw = out + ((size_t)(b * CC + c)) * NN + q0;
#pragma unroll 4
        for (int n4 = 0; n4 < 16; n4++) {
            float4 xv = *(const float4*)(xr + n4 * 4);
            float4 o;
            o.x = stage[(n4 * 4 + 0) * OSTR + c] + xv.x;
            o.y = stage[(n4 * 4 + 1) * OSTR + c] + xv.y;
            o.z = stage[(n4 * 4 + 2) * OSTR + c] + xv.z;
            o.w = stage[(n4 * 4 + 3) * OSTR + c] + xv.w;
            *(float4*)(orw + n4 * 4) = o;
        }
    }
}

// ---------------------------------------------------------------------------
extern "C" void kernel_launch(void* const* d_in, const int* in_sizes, int n_in,
                              void* d_out, int out_size)
{
    const float* x     = (const float*)d_in[0];
    const float* wq    = (const float*)d_in[1];
    const float* bq    = (const float*)d_in[2];
    const float* wk    = (const float*)d_in[3];
    const float* bk    = (const float*)d_in[4];
    const float* wv    = (const float*)d_in[5];
    const float* bv    = (const float*)d_in[6];
    const float* gamma = (const float*)d_in[7];
    float* out = (float*)d_out;

    __nv_bfloat16 *qh, *ql, *kh, *kl, *vh, *vl;
    cudaGetSymbolAddress((void**)&qh, g_qh);
    cudaGetSymbolAddress((void**)&ql, g_ql);
    cudaGetSymbolAddress((void**)&kh, g_kh);
    cudaGetSymbolAddress((void**)&kl, g_kl);
    cudaGetSymbolAddress((void**)&vh, g_vh);
    cudaGetSymbolAddress((void**)&vl, g_vl);

    dim3 blk(256);
    proj_qk<<<dim3(NN / 128, NB), blk>>>(wq, bq, x, qh, ql);
    proj_qk<<<dim3(NN / 128, NB), blk>>>(wk, bk, x, kh, kl);
    proj_v <<<dim3(NN / 128, NB, CC / 32), blk>>>(wv, bv, x, vh, vl);

    cudaFuncSetAttribute(flash_mma, cudaFuncAttributeMaxDynamicSharedMemorySize, SMEM_BYTES);
    flash_mma<<<dim3(NN / BQ, NB), blk, SMEM_BYTES>>>(x, gamma, out);
}

// round 9
// speedup vs baseline: 1.2147x; 1.2147x over previous
#include <cuda_runtime.h>
#include <cuda_bf16.h>
#include <cstdint>

#define NB 8
#define CC 256
#define NN 4096
#define DD 32
#define BQ 64
#define BK 64
#define NT (NN / BK)

// Pre-split bf16 operands (hi + lo; V is hi-only: P*Vl term dropped by analysis)
__device__ __align__(128) __nv_bfloat16 g_qh[(size_t)NB * NN * DD];
__device__ __align__(128) __nv_bfloat16 g_ql[(size_t)NB * NN * DD];
__device__ __align__(128) __nv_bfloat16 g_kh[(size_t)NB * NN * DD];
__device__ __align__(128) __nv_bfloat16 g_kl[(size_t)NB * NN * DD];
__device__ __align__(128) __nv_bfloat16 g_vh[(size_t)NB * CC * NN];  // [b][c][n]

// ---- smem layout (dynamic, bytes) ----
#define QSTR 80                    // 32 bf16 + pad (20 words)
#define KSTR 80
#define PSTR 144                   // 64 bf16 + pad (36 words, ≡4 mod 32)
#define VSTR 144
#define OSTR 260                   // stage stride (floats)
#define QH_OFF 0
#define QL_OFF 5120
#define K_OFF(buf, mat) (10240 + (buf) * 10240 + (mat) * 5120)
#define PH_OFF 30720               // 64 x 64 bf16, single buffer (sync-protected)
#define PL_OFF (PH_OFF + 9216)
#define V_OFF(buf) (49152 + (buf) * 36864)   // 256 x 64 bf16 per buf
#define STAGE_OFF 49152            // reuses V region at epilogue (66560 B <= 73728)
#define SMEM_BYTES 122880

// ---- helpers ----
__device__ __forceinline__ uint32_t smem_u32(const void* p) {
    uint32_t a;
    asm("{ .reg .u64 t; cvta.to.shared.u64 t, %1; cvt.u32.u64 %0, t; }" : "=r"(a) : "l"(p));
    return a;
}
__device__ __forceinline__ void cpa16(uint32_t dst, const void* src) {
    asm volatile("cp.async.cg.shared.global [%0], [%1], 16;" :: "r"(dst), "l"(src) : "memory");
}
__device__ __forceinline__ void cp_commit() { asm volatile("cp.async.commit_group;" ::: "memory"); }
template <int N> __device__ __forceinline__ void cp_wait() {
    asm volatile("cp.async.wait_group %0;" :: "n"(N) : "memory");
}
__device__ __forceinline__ void bar_pair(int id) {
    asm volatile("bar.sync %0, 64;" :: "r"(id) : "memory");
}
__device__ __forceinline__ void mma_bf16(float* d, const uint32_t* a, const uint32_t* b) {
    asm volatile(
        "mma.sync.aligned.m16n8k16.row.col.f32.bf16.bf16.f32 "
        "{%0,%1,%2,%3}, {%4,%5,%6,%7}, {%8,%9}, {%0,%1,%2,%3};"
        : "+f"(d[0]), "+f"(d[1]), "+f"(d[2]), "+f"(d[3])
        : "r"(a[0]), "r"(a[1]), "r"(a[2]), "r"(a[3]), "r"(b[0]), "r"(b[1]));
}
__device__ __forceinline__ uint32_t packbf(__nv_bfloat16 lo, __nv_bfloat16 hi) {
    __nv_bfloat162 t; t.x = lo; t.y = hi;
    return *(uint32_t*)&t;
}

// per-thread share of one K/V tile load (10 cp.async of 16B)
__device__ __forceinline__ void load_kv(char* smp, int b, int m0, int buf, int tid) {
#pragma unroll
    for (int it = 0; it < 2; it++) {            // K: 64 rows x 4 chunks x 2 mats
        int idx = tid + it * 256;
        int mat = idx >> 8, r = (idx >> 2) & 63, j = idx & 3;
        const __nv_bfloat16* src = (mat ? g_kl : g_kh) +
            ((size_t)(b * NN + m0 + r)) * DD + j * 8;
        cpa16(smem_u32(smp + K_OFF(buf, mat) + r * KSTR + j * 16), src);
    }
#pragma unroll
    for (int it = 0; it < 8; it++) {            // V hi only: 256 rows x 8 chunks
        int idx = tid + it * 256;
        int r = idx >> 3, j = idx & 7;
        const __nv_bfloat16* src = g_vh + ((size_t)(b * CC + r)) * NN + m0 + j * 8;
        cpa16(smem_u32(smp + V_OFF(buf) + r * VSTR + j * 16), src);
    }
}

// ---------------------------------------------------------------------------
// Projection: q/k -> [b][n][32] bf16 hi/lo
// ---------------------------------------------------------------------------
__global__ void __launch_bounds__(256) proj_qk(
    const float* __restrict__ W, const float* __restrict__ bias,
    const float* __restrict__ x,
    __nv_bfloat16* __restrict__ oh, __nv_bfloat16* __restrict__ ol)
{
    __shared__ float xs[32][128];
    __shared__ float ws[32][33];
    const int tid = threadIdx.x;
    const int b  = blockIdx.y;
    const int n0 = blockIdx.x * 128;
    const int tr = tid & 7, tn = tid >> 3;

    float acc[4][4];
#pragma unroll
    for (int i = 0; i < 4; i++) {
        float bb = bias[tr * 4 + i];
#pragma unroll
        for (int j = 0; j < 4; j++) acc[i][j] = bb;
    }
    for (int c0 = 0; c0 < CC; c0 += 32) {
#pragma unroll
        for (int k = 0; k < 16; k++) {
            int idx = tid + k * 256;
            int row = idx >> 7, col = idx & 127;
            xs[row][col] = x[((size_t)b * CC + (c0 + row)) * NN + n0 + col];
        }
#pragma unroll
        for (int k = 0; k < 4; k++) {
            int idx = tid + k * 256;
            int row = idx >> 5, col = idx & 31;
            ws[row][col] = W[(size_t)row * CC + c0 + col];
        }
        __syncthreads();
#pragma unroll 8
        for (int cc = 0; cc < 32; cc++) {
            float4 xv = *(const float4*)&xs[cc][tn * 4];
            float wr[4];
#pragma unroll
            for (int i = 0; i < 4; i++) wr[i] = ws[tr * 4 + i][cc];
#pragma unroll
            for (int i = 0; i < 4; i++) {
                acc[i][0] += wr[i] * xv.x; acc[i][1] += wr[i] * xv.y;
                acc[i][2] += wr[i] * xv.z; acc[i][3] += wr[i] * xv.w;
            }
        }
        __syncthreads();
    }
#pragma unroll
    for (int j = 0; j < 4; j++) {
        int n = n0 + tn * 4 + j;
#pragma unroll
        for (int i = 0; i < 4; i++) {
            int r = tr * 4 + i;
            float a = acc[i][j];
            __nv_bfloat16 h = __float2bfloat16(a);
            oh[((size_t)(b * NN + n)) * DD + r] = h;
            ol[((size_t)(b * NN + n)) * DD + r] = __float2bfloat16(a - __bfloat162float(h));
        }
    }
}

// ---------------------------------------------------------------------------
// Projection: v -> [b][c][n] bf16 (hi only)
// ---------------------------------------------------------------------------
__global__ void __launch_bounds__(256) proj_v(
    const float* __restrict__ W, const float* __restrict__ bias,
    const float* __restrict__ x,
    __nv_bfloat16* __restrict__ oh)
{
    __shared__ float xs[32][128];
    __shared__ float ws[32][33];
    const int tid = threadIdx.x;
    const int b  = blockIdx.y;
    const int n0 = blockIdx.x * 128;
    const int r0 = blockIdx.z * 32;
    const int tr = tid & 7, tn = tid >> 3;

    float acc[4][4];
#pragma unroll
    for (int i = 0; i < 4; i++) {
        float bb = bias[r0 + tr * 4 + i];
#pragma unroll
        for (int j = 0; j < 4; j++) acc[i][j] = bb;
    }
    for (int c0 = 0; c0 < CC; c0 += 32) {
#pragma unroll
        for (int k = 0; k < 16; k++) {
            int idx = tid + k * 256;
            int row = idx >> 7, col = idx & 127;
            xs[row][col] = x[((size_t)b * CC + (c0 + row)) * NN + n0 + col];
        }
#pragma unroll
        for (int k = 0; k < 4; k++) {
            int idx = tid + k * 256;
            int row = idx >> 5, col = idx & 31;
            ws[row][col] = W[(size_t)(r0 + row) * CC + c0 + col];
        }
        __syncthreads();
#pragma unroll 8
        for (int cc = 0; cc < 32; cc++) {
            float4 xv = *(const float4*)&xs[cc][tn * 4];
            float wr[4];
#pragma unroll
            for (int i = 0; i < 4; i++) wr[i] = ws[tr * 4 + i][cc];
#pragma unroll
            for (int i = 0; i < 4; i++) {
                acc[i][0] += wr[i] * xv.x; acc[i][1] += wr[i] * xv.y;
                acc[i][2] += wr[i] * xv.z; acc[i][3] += wr[i] * xv.w;
            }
        }
        __syncthreads();
    }
#pragma unroll
    for (int i = 0; i < 4; i++) {
        int r = r0 + tr * 4 + i;
#pragma unroll
        for (int j = 0; j < 4; j++) {
            int n = n0 + tn * 4 + j;
            oh[((size_t)(b * CC + r)) * NN + n] = __float2bfloat16(acc[i][j]);
        }
    }
}

// ---------------------------------------------------------------------------
// Flash attention: mma.sync, S de-duplicated across c-half warps (paired
// named barriers), P exchanged via smem; PV = P * bf16(V) (2 terms).
// Grid (NN/BQ, NB) = (64, 8); 256 threads = 8 warps (4 q-rows x 2 c-halves).
// ---------------------------------------------------------------------------
__global__ void __launch_bounds__(256, 1) flash_mma(
    const float* __restrict__ x, const float* __restrict__ gamma,
    float* __restrict__ out)
{
    extern __shared__ char smp[];
    const int tid  = threadIdx.x;
    const int lane = tid & 31;
    const int wid  = tid >> 5;
    const int wr   = wid >> 1;        // 0..3: q-rows  wr*16..+15
    const int wc   = wid & 1;         // 0..1: channel half AND key half for S
    const int g    = lane >> 2;       // groupID
    const int tg   = lane & 3;        // threadID-in-group
    const int b  = blockIdx.y;
    const int q0 = blockIdx.x * BQ;

    // ---- prologue: Q + tile-0 K/V ----
#pragma unroll
    for (int it = 0; it < 2; it++) {       // Q: 64 rows x 4 chunks x 2 mats
        int idx = tid + it * 256;
        int mat = idx >> 8, r = (idx >> 2) & 63, j = idx & 3;
        const __nv_bfloat16* src = (mat ? g_ql : g_qh) +
            ((size_t)(b * NN + q0 + r)) * DD + j * 8;
        cpa16(smem_u32(smp + (mat ? QL_OFF : QH_OFF) + r * QSTR + j * 16), src);
    }
    load_kv(smp, b, 0, 0, tid);
    cp_commit();
    cp_wait<0>();
    __syncthreads();

    // ---- preload Q fragments (constant across tiles) ----
    uint32_t QhA[2][4], QlA[2][4];
    {
        int rowA = wr * 16 + g, rowB = rowA + 8;
#pragma unroll
        for (int kf = 0; kf < 2; kf++) {
            int w0 = (kf * 8 + tg) * 4;
            QhA[kf][0] = *(const uint32_t*)(smp + QH_OFF + rowA * QSTR + w0);
            QhA[kf][1] = *(const uint32_t*)(smp + QH_OFF + rowB * QSTR + w0);
            QhA[kf][2] = *(const uint32_t*)(smp + QH_OFF + rowA * QSTR + w0 + 16);
            QhA[kf][3] = *(const uint32_t*)(smp + QH_OFF + rowB * QSTR + w0 + 16);
            QlA[kf][0] = *(const uint32_t*)(smp + QL_OFF + rowA * QSTR + w0);
            QlA[kf][1] = *(const uint32_t*)(smp + QL_OFF + rowB * QSTR + w0);
            QlA[kf][2] = *(const uint32_t*)(smp + QL_OFF + rowA * QSTR + w0 + 16);
            QlA[kf][3] = *(const uint32_t*)(smp + QL_OFF + rowB * QSTR + w0 + 16);
        }
    }

    float O[16][4];
#pragma unroll
    for (int i = 0; i < 16; i++)
#pragma unroll
        for (int j = 0; j < 4; j++) O[i][j] = 0.f;
    float lsumA = 0.f, lsumB = 0.f;

    // loop-invariant P smem addresses
    const int rowA = wr * 16 + g;
    char* psh_w = smp + PH_OFF + rowA * PSTR + (wc * 32 + 2 * tg) * 2;  // own write base
    char* psl_w = psh_w + (PL_OFF - PH_OFF);
    const int ko = (1 - wc) * 32;                                        // other key base
    const char* psh_r = smp + PH_OFF + rowA * PSTR + (ko + 2 * tg) * 2;
    const char* psl_r = psh_r + (PL_OFF - PH_OFF);
    const int barid = 1 + wr;

    for (int t = 0; t < NT; t++) {
        const int buf = t & 1;
        if (t) cp_wait<0>();
        __syncthreads();
        if (t + 1 < NT) { load_kv(smp, b, (t + 1) * BK, buf ^ 1, tid); cp_commit(); }

        // ---- S = Q K^T on own 32-key half; exp; own frags in regs + smem ----
        uint32_t Ph[4][2], Pl[4][2];
        {
            const char* kh = smp + K_OFF(buf, 0);
            const char* kl = smp + K_OFF(buf, 1);
#pragma unroll
            for (int nt = 0; nt < 4; nt++) {
                int krow = wc * 32 + nt * 8 + g;
                uint32_t KhB[2][2], KlB[2][2];
#pragma unroll
                for (int kf = 0; kf < 2; kf++) {
                    int w0 = (kf * 8 + tg) * 4;
                    KhB[kf][0] = *(const uint32_t*)(kh + krow * KSTR + w0);
                    KhB[kf][1] = *(const uint32_t*)(kh + krow * KSTR + w0 + 16);
                    KlB[kf][0] = *(const uint32_t*)(kl + krow * KSTR + w0);
                    KlB[kf][1] = *(const uint32_t*)(kl + krow * KSTR + w0 + 16);
                }
                float S[4] = {0.f, 0.f, 0.f, 0.f};
                mma_bf16(S, QhA[0], KhB[0]); mma_bf16(S, QhA[1], KhB[1]);
                mma_bf16(S, QlA[0], KhB[0]); mma_bf16(S, QlA[1], KhB[1]);
                mma_bf16(S, QhA[0], KlB[0]); mma_bf16(S, QhA[1], KlB[1]);

                float p0 = __expf(S[0]), p1 = __expf(S[1]);
                float p2 = __expf(S[2]), p3 = __expf(S[3]);
                lsumA += p0 + p1;
                lsumB += p2 + p3;
                __nv_bfloat16 h0 = __float2bfloat16(p0), h1 = __float2bfloat16(p1);
                __nv_bfloat16 h2 = __float2bfloat16(p2), h3 = __float2bfloat16(p3);
                uint32_t ph01 = packbf(h0, h1), ph23 = packbf(h2, h3);
                uint32_t pl01 = packbf(__float2bfloat16(p0 - __bfloat162float(h0)),
                                       __float2bfloat16(p1 - __bfloat162float(h1)));
                uint32_t pl23 = packbf(__float2bfloat16(p2 - __bfloat162float(h2)),
                                       __float2bfloat16(p3 - __bfloat162float(h3)));
                Ph[nt][0] = ph01; Ph[nt][1] = ph23;
                Pl[nt][0] = pl01; Pl[nt][1] = pl23;
                *(uint32_t*)(psh_w + nt * 16)            = ph01;
                *(uint32_t*)(psh_w + 8 * PSTR + nt * 16) = ph23;
                *(uint32_t*)(psl_w + nt * 16)            = pl01;
                *(uint32_t*)(psl_w + 8 * PSTR + nt * 16) = pl23;
            }
        }
        bar_pair(barid);   // pairwise: partner's P half now visible

        // ---- assemble full-width A-fragments: own from regs, other from smem ----
        uint32_t APh[4][4], APl[4][4];
#pragma unroll
        for (int j = 0; j < 2; j++) {
            int kown = 2 * wc + j;
            APh[kown][0] = Ph[2*j][0];   APh[kown][1] = Ph[2*j][1];
            APh[kown][2] = Ph[2*j+1][0]; APh[kown][3] = Ph[2*j+1][1];
            APl[kown][0] = Pl[2*j][0];   APl[kown][1] = Pl[2*j][1];
            APl[kown][2] = Pl[2*j+1][0]; APl[kown][3] = Pl[2*j+1][1];
            int koth = 2 * (1 - wc) + j;
            APh[koth][0] = *(const uint32_t*)(psh_r + j * 32);
            APh[koth][1] = *(const uint32_t*)(psh_r + 8 * PSTR + j * 32);
            APh[koth][2] = *(const uint32_t*)(psh_r + j * 32 + 16);
            APh[koth][3] = *(const uint32_t*)(psh_r + 8 * PSTR + j * 32 + 16);
            APl[koth][0] = *(const uint32_t*)(psl_r + j * 32);
            APl[koth][1] = *(const uint32_t*)(psl_r + 8 * PSTR + j * 32);
            APl[koth][2] = *(const uint32_t*)(psl_r + j * 32 + 16);
            APl[koth][3] = *(const uint32_t*)(psl_r + 8 * PSTR + j * 32 + 16);
        }

        // ---- O += P V^T  (Vh only; 2 terms) ----
        {
            const char* vh = smp + V_OFF(buf);
#pragma unroll
            for (int nt = 0; nt < 16; nt++) {
                int crow = wc * 128 + nt * 8 + g;
                uint32_t VhB[4][2];
#pragma unroll
                for (int kf = 0; kf < 4; kf++) {
                    int w0 = (kf * 8 + tg) * 4;
                    VhB[kf][0] = *(const uint32_t*)(vh + crow * VSTR + w0);
                    VhB[kf][1] = *(const uint32_t*)(vh + crow * VSTR + w0 + 16);
                }
#pragma unroll
                for (int kf = 0; kf < 4; kf++) {
                    mma_bf16(O[nt], APh[kf], VhB[kf]);
                    mma_bf16(O[nt], APl[kf], VhB[kf]);
                }
            }
        }
    }

    // ---- combine lsum halves + epilogue ----
    lsumA += __shfl_xor_sync(0xffffffffu, lsumA, 1);
    lsumA += __shfl_xor_sync(0xffffffffu, lsumA, 2);
    lsumB += __shfl_xor_sync(0xffffffffu, lsumB, 1);
    lsumB += __shfl_xor_sync(0xffffffffu, lsumB, 2);

    __syncthreads();                       // all P/V reads done; reuse regions
    float* lsh = (float*)(smp + PH_OFF);   // 128 floats: [keyhalf][q]
    if (tg == 0) {
        lsh[wc * 64 + wr * 16 + g]     = lsumA;
        lsh[wc * 64 + wr * 16 + 8 + g] = lsumB;
    }
    float* stage = (float*)(smp + STAGE_OFF);   // [q=64][c=256], stride OSTR
    {
        int q = wr * 16 + g;
#pragma unroll
        for (int nt = 0; nt < 16; nt++) {
            int c = wc * 128 + nt * 8 + tg * 2;
            stage[q * OSTR + c]           = O[nt][0];
            stage[q * OSTR + c + 1]       = O[nt][1];
            stage[(q + 8) * OSTR + c]     = O[nt][2];
            stage[(q + 8) * OSTR + c + 1] = O[nt][3];
        }
    }
    __syncthreads();
    const float gm = gamma[0];
    if (tid < 64) lsh[tid] = gm / (lsh[tid] + lsh[64 + tid]);   // per-q scale
    __syncthreads();

    {
        int c = tid;   // one channel row per thread
        const float* xr  = x   + ((size_t)(b * CC + c)) * NN + q0;
        float*       orw = out + ((size_t)(b * CC + c)) * NN + q0;
#pragma unroll 4
        for (int n4 = 0; n4 < 16; n4++) {
            float4 xv = *(const float4*)(xr + n4 * 4);
            float4 o;
            o.x = stage[(n4 * 4 + 0) * OSTR + c] * lsh[n4 * 4 + 0] + xv.x;
            o.y = stage[(n4 * 4 + 1) * OSTR + c] * lsh[n4 * 4 + 1] + xv.y;
            o.z = stage[(n4 * 4 + 2) * OSTR + c] * lsh[n4 * 4 + 2] + xv.z;
            o.w = stage[(n4 * 4 + 3) * OSTR + c] * lsh[n4 * 4 + 3] + xv.w;
            *(float4*)(orw + n4 * 4) = o;
        }
    }
}

// ---------------------------------------------------------------------------
extern "C" void kernel_launch(void* const* d_in, const int* in_sizes, int n_in,
                              void* d_out, int out_size)
{
    const float* x     = (const float*)d_in[0];
    const float* wq    = (const float*)d_in[1];
    const float* bq    = (const float*)d_in[2];
    const float* wk    = (const float*)d_in[3];
    const float* bk    = (const float*)d_in[4];
    const float* wv    = (const float*)d_in[5];
    const float* bv    = (const float*)d_in[6];
    const float* gamma = (const float*)d_in[7];
    float* out = (float*)d_out;

    __nv_bfloat16 *qh, *ql, *kh, *kl, *vh;
    cudaGetSymbolAddress((void**)&qh, g_qh);
    cudaGetSymbolAddress((void**)&ql, g_ql);
    cudaGetSymbolAddress((void**)&kh, g_kh);
    cudaGetSymbolAddress((void**)&kl, g_kl);
    cudaGetSymbolAddress((void**)&vh, g_vh);

    dim3 blk(256);
    proj_qk<<<dim3(NN / 128, NB), blk>>>(wq, bq, x, qh, ql);
    proj_qk<<<dim3(NN / 128, NB), blk>>>(wk, bk, x, kh, kl);
    proj_v <<<dim3(NN / 128, NB, CC / 32), blk>>>(wv, bv, x, vh);

    cudaFuncSetAttribute(flash_mma, cudaFuncAttributeMaxDynamicSharedMemorySize, SMEM_BYTES);
    flash_mma<<<dim3(NN / BQ, NB), blk, SMEM_BYTES>>>(x, gamma, out);
}